// round 4
// baseline (speedup 1.0000x reference)
#include <cuda_runtime.h>

#define S_LEN 4096
#define D_DIM 300
#define H_DIM 300
#define HU    150
#define G4    600   // 4*HU

// ---------------- scratch (static device globals; no allocation) ----------------
__device__ float g_xW[2][S_LEN * G4];        // x@W + b, per direction (bwd pre-reversed)
__device__ float g_hidden[S_LEN * H_DIM];    // [S,300]: cols 0..149 fwd, 150..299 bwd
__device__ float g_attout[S_LEN * H_DIM];    // hidden @ W_p + b_p
__device__ float g_m[S_LEN * D_DIM];         // attention m vectors
__device__ float g_coeff[S_LEN];             // secondary attention coeffs
__device__ float g_partial[64 * G4];         // deterministic reduction partials

// ---------------- helpers ----------------
__device__ __forceinline__ unsigned long long ffma2(unsigned long long a,
                                                    unsigned long long b,
                                                    unsigned long long c) {
    unsigned long long d;
    asm("fma.rn.f32x2 %0, %1, %2, %3;" : "=l"(d) : "l"(a), "l"(b), "l"(c));
    return d;
}
__device__ __forceinline__ unsigned long long pack2(float lo, float hi) {
    unsigned long long p;
    asm("mov.b64 %0, {%1, %2};" : "=l"(p) : "f"(lo), "f"(hi));
    return p;
}
__device__ __forceinline__ void unpack2(unsigned long long v, float& lo, float& hi) {
    asm("mov.b64 {%0, %1}, %2;" : "=f"(lo), "=f"(hi) : "l"(v));
}
__device__ __forceinline__ void cluster_sync_() {
    asm volatile("barrier.cluster.arrive.aligned;" ::: "memory");
    asm volatile("barrier.cluster.wait.aligned;" ::: "memory");
}
__device__ __forceinline__ float ex2f_(float x) {
    float y; asm("ex2.approx.f32 %0, %1;" : "=f"(y) : "f"(x)); return y;
}
__device__ __forceinline__ float rcpf_(float x) {
    float y; asm("rcp.approx.f32 %0, %1;" : "=f"(y) : "f"(x)); return y;
}
// sigmoid via ex2/rcp approx: rel err ~1e-7 (far inside 1e-3 budget)
__device__ __forceinline__ float sigmoid_fast(float x) {
    return rcpf_(1.0f + ex2f_(-1.4426950408889634f * x));
}
__device__ __forceinline__ float tanh_fast(float x) {
    return fmaf(2.0f, sigmoid_fast(2.0f * x), -1.0f);
}
__device__ __forceinline__ void mbar_wait(unsigned addr, unsigned par) {
    asm volatile(
        "{\n\t.reg .pred p;\n\t"
        "WAIT_%=:\n\t"
        "mbarrier.try_wait.parity.acquire.cluster.shared::cta.b64 p, [%0], %1, 0x989680;\n\t"
        "@!p bra WAIT_%=;\n\t"
        "}"
        :: "r"(addr), "r"(par) : "memory");
}

// ---------------- K1: xW = gather(emb) @ W_dir + b_dir (bwd rows pre-reversed) ----------------
__global__ __launch_bounds__(608, 2)
void xw_kernel(const int* __restrict__ sent, const float* __restrict__ E,
               const float* __restrict__ W_f, const float* __restrict__ b_f,
               const float* __restrict__ W_b, const float* __restrict__ b_b) {
    const int dir = blockIdx.y;
    const int s0  = blockIdx.x * 16;
    const float* __restrict__ W  = dir ? W_b : W_f;
    const float* __restrict__ bv = dir ? b_b : b_f;
    __shared__ float esm[16 * D_DIM];
    const int tid = threadIdx.x;
    for (int i = tid; i < 16 * D_DIM; i += 608) {
        int r = i / D_DIM, k = i - r * D_DIM;
        int srow = dir ? (S_LEN - 1 - (s0 + r)) : (s0 + r);
        esm[i] = E[(long long)sent[srow] * D_DIM + k];
    }
    __syncthreads();
    const int j = tid;
    if (j < G4) {
        float acc[16];
#pragma unroll
        for (int r = 0; r < 16; r++) acc[r] = 0.f;
        for (int k = 0; k < D_DIM; k++) {
            float w = W[k * G4 + j];
#pragma unroll
            for (int r = 0; r < 16; r++) acc[r] = fmaf(esm[r * D_DIM + k], w, acc[r]);
        }
        float bb = bv[j];
#pragma unroll
        for (int r = 0; r < 16; r++) g_xW[dir][(s0 + r) * G4 + j] = acc[r] + bb;
    }
}

// ---------------- K2: persistent biLSTM. 2 clusters of 2 CTAs (one cluster/dir). ----------------
// Thread tid<300: cell mloc = tid>>2 (0..74), gate = tid&3 (i,f,g,o). Cell's 4 gates live in
// one shuffle group -> combine in-warp, ONE __syncthreads per step.
// h ring buffer: 3 buffers x 152 floats, layout [own 75 | pad | peer 75 | pad].
// Peer h delivered via st.async + mbarrier complete_tx (no cluster.sync, no L1 flush).
__global__ void __cluster_dims__(2, 1, 1) __launch_bounds__(320, 1)
lstm_kernel(const float* __restrict__ U_f, const float* __restrict__ U_b) {
    const int dir = blockIdx.x >> 1;
    unsigned rank; asm("mov.u32 %0, %%cluster_ctarank;" : "=r"(rank));
    const int tid = threadIdx.x;
    const float* __restrict__ U  = dir ? U_b : U_f;
    const float* __restrict__ xW = g_xW[dir];

    __shared__ __align__(16) float hbuf[3][152];
    __shared__ unsigned long long mbar[3];

    for (int i = tid; i < 3 * 152; i += 320) (&hbuf[0][0])[i] = 0.f;
    unsigned mb_base = (unsigned)__cvta_generic_to_shared(&mbar[0]);
    if (tid == 0) {
#pragma unroll
        for (int b = 0; b < 3; b++)
            asm volatile("mbarrier.init.shared.b64 [%0], %1;"
                         :: "r"(mb_base + b * 8u), "r"(1u) : "memory");
    }
    __syncthreads();

    const bool active = tid < 300;
    const int g    = tid & 3;
    const int mloc = tid >> 2;                 // 0..74 when active
    const int m    = (int)rank * 75 + mloc;    // global cell index
    const int j    = g * HU + m;               // column in [0,600)

    // U columns reordered to ring-buffer h layout: pos 0..74 own cells, 76..150 peer cells
    unsigned long long u64[76];
#pragma unroll
    for (int kk = 0; kk < 76; kk++) {
        float w0 = 0.f, w1 = 0.f;
        if (active) {
            const int p0 = 2 * kk, p1 = 2 * kk + 1;
            if (p0 < 75)                      w0 = U[((int)rank * 75 + p0) * G4 + j];
            else if (p0 >= 76 && p0 < 151)    w0 = U[((1 - (int)rank) * 75 + (p0 - 76)) * G4 + j];
            if (p1 < 75)                      w1 = U[((int)rank * 75 + p1) * G4 + j];
            else if (p1 >= 76 && p1 < 151)    w1 = U[((1 - (int)rank) * 75 + (p1 - 76)) * G4 + j];
        }
        u64[kk] = pack2(w0, w1);
    }

    unsigned hbase = (unsigned)__cvta_generic_to_shared(&hbuf[0][0]);
    unsigned peer = rank ^ 1u;
    unsigned r_hbase, r_mbase;
    asm("mapa.shared::cluster.u32 %0, %1, %2;" : "=r"(r_hbase) : "r"(hbase), "r"(peer));
    asm("mapa.shared::cluster.u32 %0, %1, %2;" : "=r"(r_mbase) : "r"(mb_base), "r"(peer));

    cluster_sync_();   // one-time: zeros + mbarrier init visible cluster-wide

    float c = 0.f;
    float xw_cur = active ? xW[j] : 0.f;
    int r = 0;            // ring slot read this step (t % 3)
    unsigned par = 0;     // wait parity = ((t-1)/3) & 1
    int c3 = 0;

    for (int t = 0; t < S_LEN; t++) {
        int w = r + 1; if (w == 3) w = 0;

        // prefetch next xW row (hidden under this step's compute)
        float xw_next = 0.f;
        if (active && t + 1 < S_LEN) xw_next = xW[(t + 1) * G4 + j];

        // announce expected peer bytes for buffer w (safe: mb[w]'s previous phase
        // was observed at our wait in step t-2)
        if (tid == 0 && t + 1 < S_LEN)
            asm volatile("mbarrier.arrive.expect_tx.shared.b64 _, [%0], %1;"
                         :: "r"(mb_base + (unsigned)w * 8u), "r"(300u) : "memory");

        const float4* hp4 = (const float4*)(&hbuf[0][0] + r * 152);
        unsigned long long a0 = 0ull, a1 = 0ull, a2 = 0ull, a3 = 0ull;

        // own-half dot product (pos 0..75): needs only local data from step t-1
        if (active) {
#pragma unroll
            for (int q = 0; q < 19; q++) {
                float4 v = hp4[q];
                if (q & 1) { a2 = ffma2(u64[2 * q], pack2(v.x, v.y), a2);
                             a3 = ffma2(u64[2 * q + 1], pack2(v.z, v.w), a3); }
                else       { a0 = ffma2(u64[2 * q], pack2(v.x, v.y), a0);
                             a1 = ffma2(u64[2 * q + 1], pack2(v.z, v.w), a1); }
            }
        }

        // wait for peer h of this step (st.async'd during peer's step t-1)
        if (t > 0) {
            if (active) mbar_wait(mb_base + (unsigned)r * 8u, par);
            if (++c3 == 3) { c3 = 0; par ^= 1; }
        }

        float act = 0.f;
        if (active) {
            // peer-half dot product (pos 76..151)
#pragma unroll
            for (int q = 19; q < 38; q++) {
                float4 v = hp4[q];
                if (q & 1) { a2 = ffma2(u64[2 * q], pack2(v.x, v.y), a2);
                             a3 = ffma2(u64[2 * q + 1], pack2(v.z, v.w), a3); }
                else       { a0 = ffma2(u64[2 * q], pack2(v.x, v.y), a0);
                             a1 = ffma2(u64[2 * q + 1], pack2(v.z, v.w), a1); }
            }
            float x0, x1, y0, y1, z0, z1, q0, q1;
            unpack2(a0, x0, x1); unpack2(a1, y0, y1);
            unpack2(a2, z0, z1); unpack2(a3, q0, q1);
            float zz = xw_cur + (((x0 + x1) + (y0 + y1)) + ((z0 + z1) + (q0 + q1)));
            act = (g == 2) ? tanh_fast(zz) : sigmoid_fast(zz);
        }

        // in-warp gate exchange within aligned groups of 4 lanes
        unsigned gmask = 0xFu << (tid & 28);
        float sg = __shfl_xor_sync(gmask, act, 2);   // gate0 receives g
        float sf = __shfl_xor_sync(gmask, act, 1);   // gate0 receives f
        float so = __shfl_xor_sync(gmask, act, 3);   // gate0 receives o

        if (active && g == 0) {
            c = fmaf(sf, c, act * sg);               // c = f*c + i*g
            float hv = so * tanh_fast(c);
            hbuf[w][mloc] = hv;                      // own slot, local buffer
            if (t + 1 < S_LEN) {
                unsigned raddr = r_hbase + ((unsigned)w * 152u + 76u + (unsigned)mloc) * 4u;
                asm volatile("st.async.shared::cluster.mbarrier::complete_tx::bytes.b32 [%0], %1, [%2];"
                             :: "r"(raddr), "r"(__float_as_uint(hv)),
                                "r"(r_mbase + (unsigned)w * 8u) : "memory");
            }
            int row = dir ? (S_LEN - 1 - t) : t;
            g_hidden[row * H_DIM + dir * HU + m] = hv;
        }
        __syncthreads();   // local h stores of buffer w visible to next step's readers
        xw_cur = xw_next;
        r = w;
    }
    cluster_sync_();
}

// ---------------- K3: attout = hidden @ W_p + b_p ----------------
__global__ __launch_bounds__(320, 2)
void attdense_kernel(const float* __restrict__ W_p, const float* __restrict__ b_p) {
    const int s0 = blockIdx.x * 16;
    __shared__ float hsm[16 * H_DIM];
    const int tid = threadIdx.x;
    for (int i = tid; i < 16 * H_DIM; i += 320) hsm[i] = g_hidden[s0 * H_DIM + i];
    __syncthreads();
    const int j = tid;
    if (j < H_DIM) {
        float acc[16];
#pragma unroll
        for (int r = 0; r < 16; r++) acc[r] = 0.f;
        for (int k = 0; k < H_DIM; k++) {
            float w = W_p[k * H_DIM + j];
#pragma unroll
            for (int r = 0; r < 16; r++) acc[r] = fmaf(hsm[r * H_DIM + k], w, acc[r]);
        }
        float bb = b_p[j];
#pragma unroll
        for (int r = 0; r < 16; r++) g_attout[(s0 + r) * H_DIM + j] = acc[r] + bb;
    }
}

// ---------------- K4: per-word synonym attention + secondary coeff ----------------
__device__ __forceinline__ float block_reduce_320(float v, float* red, int lane, int wid) {
#pragma unroll
    for (int off = 16; off; off >>= 1) v += __shfl_down_sync(0xffffffffu, v, off);
    __syncthreads();
    if (lane == 0) red[wid] = v;
    __syncthreads();
    float t = 0.f;
#pragma unroll
    for (int w = 0; w < 10; w++) t += red[w];
    return t;
}

__global__ __launch_bounds__(320)
void attn_kernel(const int* __restrict__ syn_idx, const float* __restrict__ E,
                 const float* __restrict__ W_s, const float* __restrict__ b_s) {
    const int s   = blockIdx.x;
    const int tid = threadIdx.x;
    const int lane = tid & 31, wid = tid >> 5;
    __shared__ float red[10];
    const bool active = tid < D_DIM;

    float od = 0.f, hd = 0.f;
    float ev[4] = {0.f, 0.f, 0.f, 0.f};
    if (active) {
        od = g_attout[s * H_DIM + tid];
        hd = g_hidden[s * H_DIM + tid];
#pragma unroll
        for (int k = 0; k < 4; k++)
            ev[k] = E[(long long)syn_idx[s * 4 + k] * D_DIM + tid];
    }
    float sc[4];
#pragma unroll
    for (int k = 0; k < 4; k++) {
        float dot = block_reduce_320(od * ev[k], red, lane, wid);
        sc[k] = expf(dot);
    }
    float md = sc[0] * ev[0] + sc[1] * ev[1] + sc[2] * ev[2] + sc[3] * ev[3];
    if (active) g_m[s * D_DIM + tid] = md;
    float cv = active ? (hd * W_s[tid] + md * W_s[D_DIM + tid]) : 0.f;
    float tot = block_reduce_320(cv, red, lane, wid);
    if (tid == 0) g_coeff[s] = expf(tanhf(tot + b_s[0]));
}

// ---------------- K5: deterministic partial reduction of coeff * h_hat ----------------
__global__ __launch_bounds__(608)
void reduce1_kernel() {
    const int b = blockIdx.x;
    const int j = threadIdx.x;
    if (j >= G4) return;
    float acc = 0.f;
    const int s0 = b * 64;
    for (int s = s0; s < s0 + 64; s++) {
        float cf = g_coeff[s];
        float v  = (j < H_DIM) ? g_hidden[s * H_DIM + j] : g_m[s * D_DIM + (j - H_DIM)];
        acc = fmaf(cf, v, acc);
    }
    g_partial[b * G4 + j] = acc;
}

// ---------------- K6: final sum + output heads ----------------
__global__ __launch_bounds__(608)
void final_kernel(const float* __restrict__ W_emo, const float* __restrict__ b_emo,
                  const float* __restrict__ W_sent, const float* __restrict__ b_sent,
                  float* __restrict__ out) {
    __shared__ float HH[G4];
    const int j = threadIdx.x;
    if (j < G4) {
        float a = 0.f;
        for (int b = 0; b < 64; b++) a += g_partial[b * G4 + j];
        HH[j] = a;
    }
    __syncthreads();
    if (j < 8) {
        float a = b_emo[j];
        for (int k = 0; k < G4; k++) a = fmaf(HH[k], W_emo[k * 8 + j], a);
        out[j] = a;
    } else if (j == 8) {
        float a = b_sent[0];
        for (int k = 0; k < G4; k++) a = fmaf(HH[k], W_sent[k], a);
        out[8] = a;
    }
}

// ---------------- launch ----------------
extern "C" void kernel_launch(void* const* d_in, const int* in_sizes, int n_in,
                              void* d_out, int out_size) {
    const int*   sent   = (const int*)d_in[0];
    const int*   syn    = (const int*)d_in[1];
    const float* E      = (const float*)d_in[2];
    const float* W_f    = (const float*)d_in[3];
    const float* U_f    = (const float*)d_in[4];
    const float* b_f    = (const float*)d_in[5];
    const float* W_b    = (const float*)d_in[6];
    const float* U_b    = (const float*)d_in[7];
    const float* b_b    = (const float*)d_in[8];
    const float* W_p    = (const float*)d_in[9];
    const float* b_p    = (const float*)d_in[10];
    const float* W_s    = (const float*)d_in[11];
    const float* b_s    = (const float*)d_in[12];
    const float* W_emo  = (const float*)d_in[13];
    const float* b_emo  = (const float*)d_in[14];
    const float* W_sent = (const float*)d_in[15];
    const float* b_sent = (const float*)d_in[16];
    float* out = (float*)d_out;

    dim3 gxw(S_LEN / 16, 2);
    xw_kernel<<<gxw, 608>>>(sent, E, W_f, b_f, W_b, b_b);
    lstm_kernel<<<4, 320>>>(U_f, U_b);                 // 2 clusters x 2 CTAs
    attdense_kernel<<<S_LEN / 16, 320>>>(W_p, b_p);
    attn_kernel<<<S_LEN, 320>>>(syn, E, W_s, b_s);
    reduce1_kernel<<<64, 608>>>();
    final_kernel<<<1, 608>>>(W_emo, b_emo, W_sent, b_sent, out);
}